// round 1
// baseline (speedup 1.0000x reference)
#include <cuda_runtime.h>
#include <cuda_bf16.h>
#include <cstdint>

// Problem constants (fixed by the reference)
constexpr int B = 8;
constexpr int X = 2048;
constexpr int Y = 2048;
constexpr int H = 1024;

// Scratch (allocation-free: __device__ globals)
__device__ float g_sq[B * Y];   // 64 KB
__device__ float g_p [B * Y];   // 64 KB softmax weights
__device__ float g_o [B * H];   // 32 KB reduced output row per batch

// -------------------------------------------------------------------------
// K1: sq[b,y] = dot(q[b,y,:], Wq)   (Wq = W[H:2H])
// One warp per row; 8 warps (256 threads) per block; float4 loads.
// -------------------------------------------------------------------------
__global__ __launch_bounds__(256) void k_sq(const float* __restrict__ q,
                                            const float* __restrict__ W) {
    __shared__ float wq[H];
    for (int i = threadIdx.x; i < H; i += 256) wq[i] = W[H + i];
    __syncthreads();

    const int warp = threadIdx.x >> 5;
    const int lane = threadIdx.x & 31;
    const int row  = blockIdx.x * 8 + warp;          // 0 .. B*Y-1

    const float4* qr = reinterpret_cast<const float4*>(q + (size_t)row * H);
    const float4* w4 = reinterpret_cast<const float4*>(wq);

    float acc = 0.f;
#pragma unroll
    for (int i = 0; i < (H / 4) / 32; ++i) {         // 8 iterations
        float4 a  = qr[lane + i * 32];
        float4 wv = w4[lane + i * 32];
        acc += a.x * wv.x + a.y * wv.y + a.z * wv.z + a.w * wv.w;
    }
#pragma unroll
    for (int o = 16; o; o >>= 1) acc += __shfl_xor_sync(0xFFFFFFFFu, acc, o);
    if (lane == 0) g_sq[row] = acc;
}

// -------------------------------------------------------------------------
// K2: per-batch softmax over Y (shift-invariance makes sk & bias cancel).
// One block per batch, 1024 threads (2 elements each). Also zeroes g_o.
// -------------------------------------------------------------------------
__global__ __launch_bounds__(1024) void k_softmax() {
    const int b = blockIdx.x;
    const int t = threadIdx.x;
    __shared__ float red[1024];

    float a0 = g_sq[b * Y + t];
    float a1 = g_sq[b * Y + t + 1024];

    // max reduce
    red[t] = fmaxf(a0, a1);
    __syncthreads();
#pragma unroll
    for (int s = 512; s; s >>= 1) {
        if (t < s) red[t] = fmaxf(red[t], red[t + s]);
        __syncthreads();
    }
    const float m = red[0];
    __syncthreads();

    const float e0 = __expf(a0 - m);
    const float e1 = __expf(a1 - m);

    // sum reduce
    red[t] = e0 + e1;
    __syncthreads();
#pragma unroll
    for (int s = 512; s; s >>= 1) {
        if (t < s) red[t] += red[t + s];
        __syncthreads();
    }
    const float inv = 1.0f / red[0];

    g_p[b * Y + t]        = e0 * inv;
    g_p[b * Y + t + 1024] = e1 * inv;
    g_o[b * H + t]        = 0.0f;      // H == 1024 == blockDim
}

// -------------------------------------------------------------------------
// K3: o[b,h] += sum over a Y-chunk of p[b,y] * v[b,y,h]
// Grid: (H/256, B, NCH). 4 independent accumulators for MLP.
// -------------------------------------------------------------------------
constexpr int NCH = 16;
constexpr int YC  = Y / NCH;   // 128 rows per chunk

__global__ __launch_bounds__(256) void k_wv(const float* __restrict__ v) {
    const int h = blockIdx.x * 256 + threadIdx.x;
    const int b = blockIdx.y;
    const int c = blockIdx.z;

    __shared__ float ps[YC];
    if (threadIdx.x < YC) ps[threadIdx.x] = g_p[b * Y + c * YC + threadIdx.x];
    __syncthreads();

    const float* vb = v + ((size_t)b * Y + (size_t)c * YC) * H + h;

    float acc0 = 0.f, acc1 = 0.f, acc2 = 0.f, acc3 = 0.f;
#pragma unroll 4
    for (int y = 0; y < YC; y += 4) {
        acc0 += ps[y + 0] * vb[(size_t)(y + 0) * H];
        acc1 += ps[y + 1] * vb[(size_t)(y + 1) * H];
        acc2 += ps[y + 2] * vb[(size_t)(y + 2) * H];
        acc3 += ps[y + 3] * vb[(size_t)(y + 3) * H];
    }
    atomicAdd(&g_o[b * H + h], (acc0 + acc1) + (acc2 + acc3));
}

// -------------------------------------------------------------------------
// K4: out[b,x,h] = o[b,h].  One block per (b,x) row; float4 stores.
// o row (4 KB) is L2-resident after first touch.
// -------------------------------------------------------------------------
__global__ __launch_bounds__(256) void k_bcast(float* __restrict__ out) {
    const int b = blockIdx.x >> 11;                  // / X
    const float4 val = *reinterpret_cast<const float4*>(
        &g_o[(b << 10) + threadIdx.x * 4]);          // b*H + h
    reinterpret_cast<float4*>(out)[(size_t)blockIdx.x * 256 + threadIdx.x] = val;
}

// -------------------------------------------------------------------------
// Inputs (metadata order): q (B,Y,H) f32, k (B,X,H) f32 [UNUSED — cancels],
// v (B,Y,H) f32, W (2H,) f32, b () f32 [UNUSED — cancels].
// Output: (B,X,H) f32.
// -------------------------------------------------------------------------
extern "C" void kernel_launch(void* const* d_in, const int* in_sizes, int n_in,
                              void* d_out, int out_size) {
    const float* q = (const float*)d_in[0];
    const float* v = (const float*)d_in[2];
    const float* W = (const float*)d_in[3];
    float* out = (float*)d_out;

    k_sq<<<(B * Y) / 8, 256>>>(q, W);
    k_softmax<<<B, 1024>>>();
    dim3 g3(H / 256, B, NCH);
    k_wv<<<g3, 256>>>(v);
    k_bcast<<<B * X, 256>>>(out);
}